// round 15
// baseline (speedup 1.0000x reference)
#include <cuda_runtime.h>
#include <math.h>
#include <stdint.h>

#define TSEQ 2048
#define NH 16
#define NB 4
#define DHD 64
#define BHT (NB*NH)          // 64
#define DMODEL 1024
#define MROWS (NB*TSEQ)      // 8192

// Scratch (device globals: allocation-free rule)
__device__ float g_q[BHT*TSEQ*DHD];        // tf32-rna rounded by gemm epilogue
__device__ float g_k[BHT*TSEQ*DHD];        // rounded
__device__ float g_vt[BHT*DHD*TSEQ];       // rounded, d-major [bh][d][seq] (written directly by gemm0)
__device__ float g_o[MROWS*DMODEL];        // rounded by attn epilogue
__device__ float g_x[MROWS*DMODEL];        // rna-rounded x
__device__ float g_bqkv[3072*DMODEL];      // w_qkv^T, [N=3072][K=1024], rounded
__device__ float g_bproj[DMODEL*DMODEL];   // w_proj^T, [N=1024][K=1024], rounded

__device__ __forceinline__ unsigned f2t(float x){
    unsigned u; asm("cvt.rna.tf32.f32 %0, %1;" : "=r"(u) : "f"(x)); return u;
}
__device__ __forceinline__ float rnaf(float x){ return __uint_as_float(f2t(x)); }

__device__ __forceinline__ uint32_t smem_u32(const void* p){
    uint32_t a; asm("{ .reg .u64 t; cvta.to.shared.u64 t, %1; cvt.u32.u64 %0, t; }" : "=r"(a) : "l"(p));
    return a;
}
__device__ __forceinline__ void cpasync16(uint32_t s, const void* g){
    asm volatile("cp.async.cg.shared.global [%0], [%1], 16;" :: "r"(s), "l"(g));
}
__device__ __forceinline__ void cp_commit(){ asm volatile("cp.async.commit_group;" ::: "memory"); }
template<int N> __device__ __forceinline__ void cp_wait(){ asm volatile("cp.async.wait_group %0;" :: "n"(N) : "memory"); }

__device__ __forceinline__ void mma8(float* d, const unsigned* a, unsigned b0, unsigned b1){
    asm volatile("mma.sync.aligned.m16n8k8.row.col.f32.tf32.tf32.f32 "
        "{%0,%1,%2,%3},{%4,%5,%6,%7},{%8,%9},{%0,%1,%2,%3};"
        : "+f"(d[0]),"+f"(d[1]),"+f"(d[2]),"+f"(d[3])
        : "r"(a[0]),"r"(a[1]),"r"(a[2]),"r"(a[3]),"r"(b0),"r"(b1));
}
__device__ __forceinline__ void ldsm4(unsigned& r0, unsigned& r1, unsigned& r2, unsigned& r3, uint32_t addr){
    asm volatile("ldmatrix.sync.aligned.m8n8.x4.shared.b16 {%0,%1,%2,%3}, [%4];"
        : "=r"(r0), "=r"(r1), "=r"(r2), "=r"(r3) : "r"(addr));
}

// ---------------- prep kernels ----------------
__global__ void round_x_kernel(const float* __restrict__ in, float* __restrict__ out){
    int i = blockIdx.x * blockDim.x + threadIdx.x;
    float4 v = ((const float4*)in)[i];
    v.x = rnaf(v.x); v.y = rnaf(v.y); v.z = rnaf(v.z); v.w = rnaf(v.w);
    ((float4*)out)[i] = v;
}

// src: R x C row-major -> dst: C x R row-major (values rna-rounded)
__global__ void transpose_round(const float* __restrict__ src, float* __restrict__ dst, int R, int C){
    __shared__ float t[32][33];
    int c0 = blockIdx.x * 32, r0 = blockIdx.y * 32;
    int x = threadIdx.x, y = threadIdx.y;     // block (32, 8)
    #pragma unroll
    for (int i = 0; i < 32; i += 8) t[y+i][x] = src[(size_t)(r0+y+i)*C + c0 + x];
    __syncthreads();
    #pragma unroll
    for (int i = 0; i < 32; i += 8) dst[(size_t)(c0+y+i)*R + r0 + x] = rnaf(t[x][y+i]);
}

// ---------------- GEMM: 128x128 CTA, 4 warps of 64x64, cp.async 3-stage, K-tile 32 ----------------
// Software-pipelined fragments + CTA-parity K-stagger; ks0' frag load hoisted before the barrier.
#define GEMM_STAGE_B 36864
#define GEMM_SMEM (3*GEMM_STAGE_B)

template<int MODE>
__global__ __launch_bounds__(128, 2)
void gemm2(const float* __restrict__ A_, const float* __restrict__ Bt,
           const float* __restrict__ bias, float* __restrict__ Cout)
{
    extern __shared__ unsigned sm[];
    const int tid = threadIdx.x, warp = tid >> 5, lane = tid & 31;
    const int g = lane >> 2, tg = lane & 3;
    const int wm = (warp & 1) * 64, wn = (warp >> 1) * 64;
    const int row0 = blockIdx.y * 128, col0 = blockIdx.x * 128;
    const float* A = (MODE == 1) ? g_o : A_;

    // Phase stagger: co-scheduled CTAs start their circular K-walk 16 tiles apart.
    const int kstart = ((blockIdx.x + blockIdx.y) & 1) * 16;

    float acc[4][8][4];
    #pragma unroll
    for (int mi = 0; mi < 4; mi++)
        #pragma unroll
        for (int ni = 0; ni < 8; ni++)
            #pragma unroll
            for (int e = 0; e < 4; e++) acc[mi][ni][e] = 0.f;

    const uint32_t sbase = smem_u32(sm);
    const int lr = tid >> 3, lc = tid & 7;

    auto load_stage = [&](int kt, int stg){
        uint32_t sA = sbase + stg * GEMM_STAGE_B;
        uint32_t sB = sA + 18432;
        const float* ga = A  + (size_t)(row0 + lr) * 1024 + kt * 32 + lc * 4;
        const float* gb = Bt + (size_t)(col0 + lr) * 1024 + kt * 32 + lc * 4;
        uint32_t so = lr * 144 + lc * 16;
        #pragma unroll
        for (int i = 0; i < 8; i++){
            cpasync16(sA + so + i * (16*144), ga + (size_t)i * (16*1024));
            cpasync16(sB + so + i * (16*144), gb + (size_t)i * (16*1024));
        }
    };

    unsigned fA[2][4][4], fB[2][8][2];

    auto load_frags = [&](int stg, int ks, int buf){
        const unsigned* As = sm + stg * (GEMM_STAGE_B/4);
        const unsigned* Bs = As + 4608;
        const int k0 = ks * 8;
        #pragma unroll
        for (int mi = 0; mi < 4; mi++){
            const unsigned* p = As + (wm + mi*16 + g) * 36 + k0 + tg;
            fA[buf][mi][0] = p[0];
            fA[buf][mi][1] = p[8*36];
            fA[buf][mi][2] = p[4];
            fA[buf][mi][3] = p[8*36 + 4];
        }
        #pragma unroll
        for (int ni = 0; ni < 8; ni++){
            const unsigned* p = Bs + (wn + ni*8 + g) * 36 + k0 + tg;
            fB[buf][ni][0] = p[0];
            fB[buf][ni][1] = p[4];
        }
    };
    auto do_mmas = [&](int buf){
        #pragma unroll
        for (int mi = 0; mi < 4; mi++)
            #pragma unroll
            for (int ni = 0; ni < 8; ni++)
                mma8(acc[mi][ni], fA[buf][mi], fB[buf][ni][0], fB[buf][ni][1]);
    };

    load_stage(kstart, 0); cp_commit();
    load_stage((kstart + 1) & 31, 1); cp_commit();
    cp_wait<1>();
    __syncthreads();
    load_frags(0, 0, 0);            // ks0 of first tile -> buf 0

    #pragma unroll 1
    for (int it = 0; it < 32; it++){
        const int stg = it % 3;
        #pragma unroll
        for (int ks = 1; ks < 4; ks++){
            load_frags(stg, ks, ks & 1);
            do_mmas((ks - 1) & 1);
        }
        if (it < 31){
            if (it + 2 < 32) load_stage((kstart + it + 2) & 31, (it + 2) % 3);
            cp_commit();
            do_mmas(1);
            cp_wait<1>();                        // stage (it+1)%3 data arrived
            load_frags((it + 1) % 3, 0, 0);      // hoisted: needs cp_wait only, not the barrier
            __syncthreads();                     // protects next iteration's load_stage writes
        } else {
            do_mmas(1);
        }
    }

    // epilogue
    if (MODE == 0){
        const int colb = col0 + wn;
        const int part = colb >> 10;               // 0:q 1:k 2:v
        const int h = (colb & 1023) >> 6;
        const int b = row0 >> 11;
        if (part < 2){
            float* dst0 = (part == 0) ? g_q : g_k;
            #pragma unroll
            for (int mi = 0; mi < 4; mi++){
                const int t = (row0 + wm + mi*16 + g) & 2047;
                float* p0 = dst0 + ((size_t)((b << 4) + h) * TSEQ + t) * DHD;
                float* p1 = p0 + 8 * DHD;
                #pragma unroll
                for (int ni = 0; ni < 8; ni++){
                    const int d = ni*8 + 2*tg;
                    *(float2*)(p0 + d) = make_float2(rnaf(acc[mi][ni][0]), rnaf(acc[mi][ni][1]));
                    *(float2*)(p1 + d) = make_float2(rnaf(acc[mi][ni][2]), rnaf(acc[mi][ni][3]));
                }
            }
        } else {
            // V: write directly d-major into g_vt[bh][d][t]
            float* vt0 = g_vt + (size_t)((b << 4) + h) * DHD * TSEQ;
            #pragma unroll
            for (int mi = 0; mi < 4; mi++){
                const int t = (row0 + wm + mi*16 + g) & 2047;
                #pragma unroll
                for (int ni = 0; ni < 8; ni++){
                    const int d = ni*8 + 2*tg;
                    float* p = vt0 + (size_t)d * TSEQ + t;
                    p[0]            = rnaf(acc[mi][ni][0]);
                    p[TSEQ]         = rnaf(acc[mi][ni][1]);
                    p[8]            = rnaf(acc[mi][ni][2]);
                    p[TSEQ + 8]     = rnaf(acc[mi][ni][3]);
                }
            }
        }
    } else {
        #pragma unroll
        for (int mi = 0; mi < 4; mi++){
            const int r = row0 + wm + mi*16 + g;
            #pragma unroll
            for (int ni = 0; ni < 8; ni++){
                const int c = col0 + wn + ni*8 + 2*tg;
                float2 bv = *(const float2*)(bias + c);
                *(float2*)(Cout + (size_t)r*1024 + c) =
                    make_float2(acc[mi][ni][0] + bv.x, acc[mi][ni][1] + bv.y);
                *(float2*)(Cout + (size_t)(r+8)*1024 + c) =
                    make_float2(acc[mi][ni][2] + bv.x, acc[mi][ni][3] + bv.y);
            }
        }
    }
}

// ---------------- attention: q-tile 64, 4 warps, K+V double-buffered, P in registers, LPT order ----------------
#define KSW(r,c) ((r)*64 + ((c) ^ ((((r)&7))<<2)))

// dynamic smem (unsigned units): K0 @0, K1 @4096, V0 @8192, V1 @12288 (64KB)
#define ATTN_SMEM 65536

__global__ __launch_bounds__(128, 3)
void attn_kernel()
{
    extern __shared__ unsigned smA[];

    // LPT: longest CTAs (largest qt) launch first; shortest fill the tail.
    const int qt = 31 - blockIdx.x, bh = blockIdx.y;
    const int tid = threadIdx.x, warp = tid >> 5, lane = tid & 31;
    const int g = lane >> 2, tg = lane & 3;
    const float* Qp  = g_q  + (size_t)bh * TSEQ * DHD;
    const float* Kp  = g_k  + (size_t)bh * TSEQ * DHD;
    const float* Vtp = g_vt + (size_t)bh * DHD * TSEQ;
    const int qrow0 = qt*64 + warp*16;
    const uint32_t sbase = smem_u32(smA);

    // ldmatrix selectors
    const int lrow = ((lane >> 3) & 1) * 8 + (lane & 7);
    const int lcol = (lane >> 4) << 2;

    // P shuffle-transpose selectors (C-frag -> A-frag within warp)
    const int srcA = (g << 2) + (tg >> 1);
    const int srcB = srcA + 2;
    const bool todd = (tg & 1);

    // per-thread chunk coords for tile loads
    const int cr = tid >> 4, cc4 = (tid & 15) * 4;

    auto ld_k = [&](int kt, int buf){
        const float* src = Kp + (size_t)kt*64*DHD + cr*DHD + cc4;
        uint32_t db = sbase + buf*16384;
        #pragma unroll
        for (int i = 0; i < 8; i++)
            cpasync16(db + 4u*KSW(cr + i*8, cc4), src + (size_t)i*8*DHD);
    };
    auto ld_v = [&](int kt, int buf){
        const float* src = Vtp + (size_t)cr*TSEQ + kt*64 + cc4;
        uint32_t db = sbase + 32768 + buf*16384;
        #pragma unroll
        for (int i = 0; i < 8; i++)
            cpasync16(db + 4u*KSW(cr + i*8, cc4), src + (size_t)i*8*TSEQ);
    };

    // Q fragments (pre-rounded tf32; *0.125 exact)
    unsigned qa[8][4];
    #pragma unroll
    for (int ks = 0; ks < 8; ks++){
        int d = ks*8;
        qa[ks][0] = __float_as_uint(Qp[(size_t)(qrow0+g  )*DHD + d+tg  ] * 0.125f);
        qa[ks][1] = __float_as_uint(Qp[(size_t)(qrow0+g+8)*DHD + d+tg  ] * 0.125f);
        qa[ks][2] = __float_as_uint(Qp[(size_t)(qrow0+g  )*DHD + d+tg+4] * 0.125f);
        qa[ks][3] = __float_as_uint(Qp[(size_t)(qrow0+g+8)*DHD + d+tg+4] * 0.125f);
    }

    float o[8][4];
    #pragma unroll
    for (int ni = 0; ni < 8; ni++){ o[ni][0]=0.f; o[ni][1]=0.f; o[ni][2]=0.f; o[ni][3]=0.f; }
    float mrow0 = -1e30f, mrow1 = -1e30f, lrow0 = 0.f, lrow1 = 0.f;

    ld_k(0, 0); ld_v(0, 0); cp_commit();

    #pragma unroll 1
    for (int kt = 0; kt <= qt; ++kt){
        cp_wait<0>();
        __syncthreads();

        if (kt < qt){
            ld_k(kt + 1, (kt + 1) & 1);
            ld_v(kt + 1, (kt + 1) & 1);
        }
        cp_commit();

        const uint32_t kbase = sbase + (kt & 1) * 16384;
        const uint32_t vbase = sbase + 32768 + (kt & 1) * 16384;

        // S = Q K^T
        float s[8][4];
        #pragma unroll
        for (int nt = 0; nt < 8; nt++){ s[nt][0]=0.f; s[nt][1]=0.f; s[nt][2]=0.f; s[nt][3]=0.f; }
        #pragma unroll
        for (int ks = 0; ks < 8; ks++){
            #pragma unroll
            for (int np = 0; np < 4; np++){
                unsigned b0, b1, b2, b3;
                ldsm4(b0, b1, b2, b3, kbase + 4u*KSW(np*16 + lrow, ks*8 + lcol));
                mma8(s[2*np  ], qa[ks], b0, b2);
                mma8(s[2*np+1], qa[ks], b1, b3);
            }
        }

        if (kt == qt){
            const int rb = warp*16 + g;
            #pragma unroll
            for (int nt = 0; nt < 8; nt++){
                int c = nt*8 + 2*tg;
                if (c   > rb  ) s[nt][0] = -1e30f;
                if (c+1 > rb  ) s[nt][1] = -1e30f;
                if (c   > rb+8) s[nt][2] = -1e30f;
                if (c+1 > rb+8) s[nt][3] = -1e30f;
            }
        }

        // online softmax (rows g, g+8)
        float mx0 = -1e30f, mx1 = -1e30f;
        #pragma unroll
        for (int nt = 0; nt < 8; nt++){
            mx0 = fmaxf(mx0, fmaxf(s[nt][0], s[nt][1]));
            mx1 = fmaxf(mx1, fmaxf(s[nt][2], s[nt][3]));
        }
        mx0 = fmaxf(mx0, __shfl_xor_sync(0xffffffffu, mx0, 1));
        mx0 = fmaxf(mx0, __shfl_xor_sync(0xffffffffu, mx0, 2));
        mx1 = fmaxf(mx1, __shfl_xor_sync(0xffffffffu, mx1, 1));
        mx1 = fmaxf(mx1, __shfl_xor_sync(0xffffffffu, mx1, 2));
        float mn0 = fmaxf(mrow0, mx0), mn1 = fmaxf(mrow1, mx1);
        float sc0 = __expf(mrow0 - mn0), sc1 = __expf(mrow1 - mn1);

        unsigned pe[8][4];
        float sum0 = 0.f, sum1 = 0.f;
        #pragma unroll
        for (int nt = 0; nt < 8; nt++){
            float p00 = __expf(s[nt][0] - mn0);
            float p01 = __expf(s[nt][1] - mn0);
            float p10 = __expf(s[nt][2] - mn1);
            float p11 = __expf(s[nt][3] - mn1);
            sum0 += p00 + p01; sum1 += p10 + p11;
            pe[nt][0] = f2t(p00);
            pe[nt][1] = f2t(p01);
            pe[nt][2] = f2t(p10);
            pe[nt][3] = f2t(p11);
        }
        sum0 += __shfl_xor_sync(0xffffffffu, sum0, 1);
        sum0 += __shfl_xor_sync(0xffffffffu, sum0, 2);
        sum1 += __shfl_xor_sync(0xffffffffu, sum1, 1);
        sum1 += __shfl_xor_sync(0xffffffffu, sum1, 2);
        lrow0 = lrow0 * sc0 + sum0;
        lrow1 = lrow1 * sc1 + sum1;
        mrow0 = mn0; mrow1 = mn1;
        #pragma unroll
        for (int nt = 0; nt < 8; nt++){
            o[nt][0] *= sc0; o[nt][1] *= sc0;
            o[nt][2] *= sc1; o[nt][3] *= sc1;
        }

        // O += P V  (P A-fragments via in-warp shuffle transpose; V via ldmatrix)
        #pragma unroll
        for (int k2 = 0; k2 < 8; k2++){
            unsigned pa[4];
            unsigned v0 = __shfl_sync(0xffffffffu, pe[k2][0], srcA);
            unsigned v1 = __shfl_sync(0xffffffffu, pe[k2][1], srcA);
            pa[0] = todd ? v1 : v0;
            unsigned w0 = __shfl_sync(0xffffffffu, pe[k2][2], srcA);
            unsigned w1 = __shfl_sync(0xffffffffu, pe[k2][3], srcA);
            pa[1] = todd ? w1 : w0;
            unsigned x0 = __shfl_sync(0xffffffffu, pe[k2][0], srcB);
            unsigned x1 = __shfl_sync(0xffffffffu, pe[k2][1], srcB);
            pa[2] = todd ? x1 : x0;
            unsigned y0 = __shfl_sync(0xffffffffu, pe[k2][2], srcB);
            unsigned y1 = __shfl_sync(0xffffffffu, pe[k2][3], srcB);
            pa[3] = todd ? y1 : y0;
            #pragma unroll
            for (int np = 0; np < 4; np++){
                unsigned u0, u1, u2, u3;
                ldsm4(u0, u1, u2, u3, vbase + 4u*KSW(np*16 + lrow, k2*8 + lcol));
                mma8(o[2*np  ], pa, u0, u2);
                mma8(o[2*np+1], pa, u1, u3);
            }
        }
    }

    // epilogue: O /= l, rna-rounded
    float i0 = 1.f / lrow0, i1 = 1.f / lrow1;
    int b = bh >> 4, h = bh & 15;
    float* Op  = g_o + (size_t)(b*TSEQ + qrow0 + g)*DMODEL + h*64;
    float* Op8 = Op + (size_t)8*DMODEL;
    #pragma unroll
    for (int nt = 0; nt < 8; nt++){
        int d = nt*8 + 2*tg;
        Op [d]   = rnaf(o[nt][0] * i0);
        Op [d+1] = rnaf(o[nt][1] * i0);
        Op8[d]   = rnaf(o[nt][2] * i1);
        Op8[d+1] = rnaf(o[nt][3] * i1);
    }
}

extern "C" void kernel_launch(void* const* d_in, const int* in_sizes, int n_in,
                              void* d_out, int out_size)
{
    const float* x     = (const float*)d_in[0];
    const float* wqkv  = (const float*)d_in[1];
    const float* wproj = (const float*)d_in[2];
    const float* bproj = (const float*)d_in[3];
    float* out = (float*)d_out;

    cudaFuncSetAttribute(gemm2<0>, cudaFuncAttributeMaxDynamicSharedMemorySize, GEMM_SMEM);
    cudaFuncSetAttribute(gemm2<1>, cudaFuncAttributeMaxDynamicSharedMemorySize, GEMM_SMEM);
    cudaFuncSetAttribute(attn_kernel, cudaFuncAttributeMaxDynamicSharedMemorySize, ATTN_SMEM);

    float* px;  cudaGetSymbolAddress((void**)&px,  g_x);
    float* pbq; cudaGetSymbolAddress((void**)&pbq, g_bqkv);
    float* pbp; cudaGetSymbolAddress((void**)&pbp, g_bproj);

    round_x_kernel<<<MROWS*DMODEL/4/256, 256>>>(x, px);
    transpose_round<<<dim3(3072/32, 1024/32), dim3(32, 8)>>>(wqkv, pbq, 1024, 3072);
    transpose_round<<<dim3(1024/32, 1024/32), dim3(32, 8)>>>(wproj, pbp, 1024, 1024);

    gemm2<0><<<dim3(24, 64), 128, GEMM_SMEM>>>(px, pbq, nullptr, nullptr);
    attn_kernel<<<dim3(32, 64), 128, ATTN_SMEM>>>();
    gemm2<1><<<dim3(8, 64), 128, GEMM_SMEM>>>(nullptr, pbp, bproj, out);
}

// round 16
// speedup vs baseline: 1.0090x; 1.0090x over previous
#include <cuda_runtime.h>
#include <math.h>
#include <stdint.h>

#define TSEQ 2048
#define NH 16
#define NB 4
#define DHD 64
#define BHT (NB*NH)          // 64
#define DMODEL 1024
#define MROWS (NB*TSEQ)      // 8192

// Scratch (device globals: allocation-free rule)
__device__ float g_q[BHT*TSEQ*DHD];        // tf32-rna rounded by gemm epilogue
__device__ float g_k[BHT*TSEQ*DHD];        // rounded
__device__ float g_vt[BHT*DHD*TSEQ];       // rounded, d-major [bh][d][seq] (written directly by gemm0)
__device__ float g_o[MROWS*DMODEL];        // rounded by attn epilogue
__device__ float g_bqkv[3072*DMODEL];      // w_qkv^T, [N=3072][K=1024], rounded
__device__ float g_bproj[DMODEL*DMODEL];   // w_proj^T, [N=1024][K=1024], rounded

__device__ __forceinline__ unsigned f2t(float x){
    unsigned u; asm("cvt.rna.tf32.f32 %0, %1;" : "=r"(u) : "f"(x)); return u;
}
__device__ __forceinline__ float rnaf(float x){ return __uint_as_float(f2t(x)); }

__device__ __forceinline__ uint32_t smem_u32(const void* p){
    uint32_t a; asm("{ .reg .u64 t; cvta.to.shared.u64 t, %1; cvt.u32.u64 %0, t; }" : "=r"(a) : "l"(p));
    return a;
}
__device__ __forceinline__ void cpasync16(uint32_t s, const void* g){
    asm volatile("cp.async.cg.shared.global [%0], [%1], 16;" :: "r"(s), "l"(g));
}
__device__ __forceinline__ void cp_commit(){ asm volatile("cp.async.commit_group;" ::: "memory"); }
template<int N> __device__ __forceinline__ void cp_wait(){ asm volatile("cp.async.wait_group %0;" :: "n"(N) : "memory"); }

__device__ __forceinline__ void mma8(float* d, const unsigned* a, unsigned b0, unsigned b1){
    asm volatile("mma.sync.aligned.m16n8k8.row.col.f32.tf32.tf32.f32 "
        "{%0,%1,%2,%3},{%4,%5,%6,%7},{%8,%9},{%0,%1,%2,%3};"
        : "+f"(d[0]),"+f"(d[1]),"+f"(d[2]),"+f"(d[3])
        : "r"(a[0]),"r"(a[1]),"r"(a[2]),"r"(a[3]),"r"(b0),"r"(b1));
}
__device__ __forceinline__ void ldsm4(unsigned& r0, unsigned& r1, unsigned& r2, unsigned& r3, uint32_t addr){
    asm volatile("ldmatrix.sync.aligned.m8n8.x4.shared.b16 {%0,%1,%2,%3}, [%4];"
        : "=r"(r0), "=r"(r1), "=r"(r2), "=r"(r3) : "r"(addr));
}

// ---------------- prep kernels ----------------
// src: R x C row-major -> dst: C x R row-major (values rna-rounded)
__global__ void transpose_round(const float* __restrict__ src, float* __restrict__ dst, int R, int C){
    __shared__ float t[32][33];
    int c0 = blockIdx.x * 32, r0 = blockIdx.y * 32;
    int x = threadIdx.x, y = threadIdx.y;     // block (32, 8)
    #pragma unroll
    for (int i = 0; i < 32; i += 8) t[y+i][x] = src[(size_t)(r0+y+i)*C + c0 + x];
    __syncthreads();
    #pragma unroll
    for (int i = 0; i < 32; i += 8) dst[(size_t)(c0+y+i)*R + r0 + x] = rnaf(t[x][y+i]);
}

// ---------------- GEMM: 128x128 CTA, 4 warps of 64x64, cp.async 3-stage, K-tile 32 ----------------
// Software-pipelined fragments + CTA-parity K-stagger.
// MODE 0: A = raw x, rna-rounding fused into A-fragment loads; epilogue scatters q/k/vt.
// MODE 1: A = g_o (pre-rounded); +bias -> Cout.
#define GEMM_STAGE_B 36864
#define GEMM_SMEM (3*GEMM_STAGE_B)

template<int MODE>
__global__ __launch_bounds__(128, 2)
void gemm2(const float* __restrict__ A_, const float* __restrict__ Bt,
           const float* __restrict__ bias, float* __restrict__ Cout)
{
    extern __shared__ unsigned sm[];
    const int tid = threadIdx.x, warp = tid >> 5, lane = tid & 31;
    const int g = lane >> 2, tg = lane & 3;
    const int wm = (warp & 1) * 64, wn = (warp >> 1) * 64;
    const int row0 = blockIdx.y * 128, col0 = blockIdx.x * 128;
    const float* A = (MODE == 1) ? g_o : A_;

    // Phase stagger: co-scheduled CTAs start their circular K-walk 16 tiles apart.
    const int kstart = ((blockIdx.x + blockIdx.y) & 1) * 16;

    float acc[4][8][4];
    #pragma unroll
    for (int mi = 0; mi < 4; mi++)
        #pragma unroll
        for (int ni = 0; ni < 8; ni++)
            #pragma unroll
            for (int e = 0; e < 4; e++) acc[mi][ni][e] = 0.f;

    const uint32_t sbase = smem_u32(sm);
    const int lr = tid >> 3, lc = tid & 7;

    auto load_stage = [&](int kt, int stg){
        uint32_t sA = sbase + stg * GEMM_STAGE_B;
        uint32_t sB = sA + 18432;
        const float* ga = A  + (size_t)(row0 + lr) * 1024 + kt * 32 + lc * 4;
        const float* gb = Bt + (size_t)(col0 + lr) * 1024 + kt * 32 + lc * 4;
        uint32_t so = lr * 144 + lc * 16;
        #pragma unroll
        for (int i = 0; i < 8; i++){
            cpasync16(sA + so + i * (16*144), ga + (size_t)i * (16*1024));
            cpasync16(sB + so + i * (16*144), gb + (size_t)i * (16*1024));
        }
    };

    unsigned fA[2][4][4], fB[2][8][2];

    // MODE 0: A bytes are raw fp32 from x -> apply cvt.rna here (bit-identical to pre-rounding).
    auto ra = [&](unsigned v) -> unsigned {
        return (MODE == 0) ? f2t(__uint_as_float(v)) : v;
    };

    auto load_frags = [&](int stg, int ks, int buf){
        const unsigned* As = sm + stg * (GEMM_STAGE_B/4);
        const unsigned* Bs = As + 4608;
        const int k0 = ks * 8;
        #pragma unroll
        for (int mi = 0; mi < 4; mi++){
            const unsigned* p = As + (wm + mi*16 + g) * 36 + k0 + tg;
            fA[buf][mi][0] = ra(p[0]);
            fA[buf][mi][1] = ra(p[8*36]);
            fA[buf][mi][2] = ra(p[4]);
            fA[buf][mi][3] = ra(p[8*36 + 4]);
        }
        #pragma unroll
        for (int ni = 0; ni < 8; ni++){
            const unsigned* p = Bs + (wn + ni*8 + g) * 36 + k0 + tg;
            fB[buf][ni][0] = p[0];
            fB[buf][ni][1] = p[4];
        }
    };
    auto do_mmas = [&](int buf){
        #pragma unroll
        for (int mi = 0; mi < 4; mi++)
            #pragma unroll
            for (int ni = 0; ni < 8; ni++)
                mma8(acc[mi][ni], fA[buf][mi], fB[buf][ni][0], fB[buf][ni][1]);
    };

    load_stage(kstart, 0); cp_commit();
    load_stage((kstart + 1) & 31, 1); cp_commit();
    cp_wait<1>();
    __syncthreads();
    load_frags(0, 0, 0);            // ks0 of first tile -> buf 0

    #pragma unroll 1
    for (int it = 0; it < 32; it++){
        const int stg = it % 3;
        #pragma unroll
        for (int ks = 1; ks < 4; ks++){
            load_frags(stg, ks, ks & 1);
            do_mmas((ks - 1) & 1);
        }
        if (it < 31){
            if (it + 2 < 32) load_stage((kstart + it + 2) & 31, (it + 2) % 3);
            cp_commit();
            do_mmas(1);
            cp_wait<1>();
            __syncthreads();                     // required before reading other threads' cp.async data
            load_frags((it + 1) % 3, 0, 0);
        } else {
            do_mmas(1);
        }
    }

    // epilogue
    if (MODE == 0){
        const int colb = col0 + wn;
        const int part = colb >> 10;               // 0:q 1:k 2:v
        const int h = (colb & 1023) >> 6;
        const int b = row0 >> 11;
        if (part < 2){
            float* dst0 = (part == 0) ? g_q : g_k;
            #pragma unroll
            for (int mi = 0; mi < 4; mi++){
                const int t = (row0 + wm + mi*16 + g) & 2047;
                float* p0 = dst0 + ((size_t)((b << 4) + h) * TSEQ + t) * DHD;
                float* p1 = p0 + 8 * DHD;
                #pragma unroll
                for (int ni = 0; ni < 8; ni++){
                    const int d = ni*8 + 2*tg;
                    *(float2*)(p0 + d) = make_float2(rnaf(acc[mi][ni][0]), rnaf(acc[mi][ni][1]));
                    *(float2*)(p1 + d) = make_float2(rnaf(acc[mi][ni][2]), rnaf(acc[mi][ni][3]));
                }
            }
        } else {
            // V: write directly d-major into g_vt[bh][d][t]
            float* vt0 = g_vt + (size_t)((b << 4) + h) * DHD * TSEQ;
            #pragma unroll
            for (int mi = 0; mi < 4; mi++){
                const int t = (row0 + wm + mi*16 + g) & 2047;
                #pragma unroll
                for (int ni = 0; ni < 8; ni++){
                    const int d = ni*8 + 2*tg;
                    float* p = vt0 + (size_t)d * TSEQ + t;
                    p[0]            = rnaf(acc[mi][ni][0]);
                    p[TSEQ]         = rnaf(acc[mi][ni][1]);
                    p[8]            = rnaf(acc[mi][ni][2]);
                    p[TSEQ + 8]     = rnaf(acc[mi][ni][3]);
                }
            }
        }
    } else {
        #pragma unroll
        for (int mi = 0; mi < 4; mi++){
            const int r = row0 + wm + mi*16 + g;
            #pragma unroll
            for (int ni = 0; ni < 8; ni++){
                const int c = col0 + wn + ni*8 + 2*tg;
                float2 bv = *(const float2*)(bias + c);
                *(float2*)(Cout + (size_t)r*1024 + c) =
                    make_float2(acc[mi][ni][0] + bv.x, acc[mi][ni][1] + bv.y);
                *(float2*)(Cout + (size_t)(r+8)*1024 + c) =
                    make_float2(acc[mi][ni][2] + bv.x, acc[mi][ni][3] + bv.y);
            }
        }
    }
}

// ---------------- attention: q-tile 64, 4 warps, K+V double-buffered, P in registers, LPT order ----------------
#define KSW(r,c) ((r)*64 + ((c) ^ ((((r)&7))<<2)))

// dynamic smem (unsigned units): K0 @0, K1 @4096, V0 @8192, V1 @12288 (64KB)
#define ATTN_SMEM 65536

__global__ __launch_bounds__(128, 3)
void attn_kernel()
{
    extern __shared__ unsigned smA[];

    // LPT: longest CTAs (largest qt) launch first; shortest fill the tail.
    const int qt = 31 - blockIdx.x, bh = blockIdx.y;
    const int tid = threadIdx.x, warp = tid >> 5, lane = tid & 31;
    const int g = lane >> 2, tg = lane & 3;
    const float* Qp  = g_q  + (size_t)bh * TSEQ * DHD;
    const float* Kp  = g_k  + (size_t)bh * TSEQ * DHD;
    const float* Vtp = g_vt + (size_t)bh * DHD * TSEQ;
    const int qrow0 = qt*64 + warp*16;
    const uint32_t sbase = smem_u32(smA);

    // ldmatrix selectors
    const int lrow = ((lane >> 3) & 1) * 8 + (lane & 7);
    const int lcol = (lane >> 4) << 2;

    // P shuffle-transpose selectors (C-frag -> A-frag within warp)
    const int srcA = (g << 2) + (tg >> 1);
    const int srcB = srcA + 2;
    const bool todd = (tg & 1);

    // per-thread chunk coords for tile loads
    const int cr = tid >> 4, cc4 = (tid & 15) * 4;

    auto ld_k = [&](int kt, int buf){
        const float* src = Kp + (size_t)kt*64*DHD + cr*DHD + cc4;
        uint32_t db = sbase + buf*16384;
        #pragma unroll
        for (int i = 0; i < 8; i++)
            cpasync16(db + 4u*KSW(cr + i*8, cc4), src + (size_t)i*8*DHD);
    };
    auto ld_v = [&](int kt, int buf){
        const float* src = Vtp + (size_t)cr*TSEQ + kt*64 + cc4;
        uint32_t db = sbase + 32768 + buf*16384;
        #pragma unroll
        for (int i = 0; i < 8; i++)
            cpasync16(db + 4u*KSW(cr + i*8, cc4), src + (size_t)i*8*TSEQ);
    };

    // Q fragments (pre-rounded tf32; *0.125 exact)
    unsigned qa[8][4];
    #pragma unroll
    for (int ks = 0; ks < 8; ks++){
        int d = ks*8;
        qa[ks][0] = __float_as_uint(Qp[(size_t)(qrow0+g  )*DHD + d+tg  ] * 0.125f);
        qa[ks][1] = __float_as_uint(Qp[(size_t)(qrow0+g+8)*DHD + d+tg  ] * 0.125f);
        qa[ks][2] = __float_as_uint(Qp[(size_t)(qrow0+g  )*DHD + d+tg+4] * 0.125f);
        qa[ks][3] = __float_as_uint(Qp[(size_t)(qrow0+g+8)*DHD + d+tg+4] * 0.125f);
    }

    float o[8][4];
    #pragma unroll
    for (int ni = 0; ni < 8; ni++){ o[ni][0]=0.f; o[ni][1]=0.f; o[ni][2]=0.f; o[ni][3]=0.f; }
    float mrow0 = -1e30f, mrow1 = -1e30f, lrow0 = 0.f, lrow1 = 0.f;

    ld_k(0, 0); ld_v(0, 0); cp_commit();

    #pragma unroll 1
    for (int kt = 0; kt <= qt; ++kt){
        cp_wait<0>();
        __syncthreads();

        if (kt < qt){
            ld_k(kt + 1, (kt + 1) & 1);
            ld_v(kt + 1, (kt + 1) & 1);
        }
        cp_commit();

        const uint32_t kbase = sbase + (kt & 1) * 16384;
        const uint32_t vbase = sbase + 32768 + (kt & 1) * 16384;

        // S = Q K^T
        float s[8][4];
        #pragma unroll
        for (int nt = 0; nt < 8; nt++){ s[nt][0]=0.f; s[nt][1]=0.f; s[nt][2]=0.f; s[nt][3]=0.f; }
        #pragma unroll
        for (int ks = 0; ks < 8; ks++){
            #pragma unroll
            for (int np = 0; np < 4; np++){
                unsigned b0, b1, b2, b3;
                ldsm4(b0, b1, b2, b3, kbase + 4u*KSW(np*16 + lrow, ks*8 + lcol));
                mma8(s[2*np  ], qa[ks], b0, b2);
                mma8(s[2*np+1], qa[ks], b1, b3);
            }
        }

        if (kt == qt){
            const int rb = warp*16 + g;
            #pragma unroll
            for (int nt = 0; nt < 8; nt++){
                int c = nt*8 + 2*tg;
                if (c   > rb  ) s[nt][0] = -1e30f;
                if (c+1 > rb  ) s[nt][1] = -1e30f;
                if (c   > rb+8) s[nt][2] = -1e30f;
                if (c+1 > rb+8) s[nt][3] = -1e30f;
            }
        }

        // online softmax (rows g, g+8)
        float mx0 = -1e30f, mx1 = -1e30f;
        #pragma unroll
        for (int nt = 0; nt < 8; nt++){
            mx0 = fmaxf(mx0, fmaxf(s[nt][0], s[nt][1]));
            mx1 = fmaxf(mx1, fmaxf(s[nt][2], s[nt][3]));
        }
        mx0 = fmaxf(mx0, __shfl_xor_sync(0xffffffffu, mx0, 1));
        mx0 = fmaxf(mx0, __shfl_xor_sync(0xffffffffu, mx0, 2));
        mx1 = fmaxf(mx1, __shfl_xor_sync(0xffffffffu, mx1, 1));
        mx1 = fmaxf(mx1, __shfl_xor_sync(0xffffffffu, mx1, 2));
        float mn0 = fmaxf(mrow0, mx0), mn1 = fmaxf(mrow1, mx1);
        float sc0 = __expf(mrow0 - mn0), sc1 = __expf(mrow1 - mn1);

        unsigned pe[8][4];
        float sum0 = 0.f, sum1 = 0.f;
        #pragma unroll
        for (int nt = 0; nt < 8; nt++){
            float p00 = __expf(s[nt][0] - mn0);
            float p01 = __expf(s[nt][1] - mn0);
            float p10 = __expf(s[nt][2] - mn1);
            float p11 = __expf(s[nt][3] - mn1);
            sum0 += p00 + p01; sum1 += p10 + p11;
            pe[nt][0] = f2t(p00);
            pe[nt][1] = f2t(p01);
            pe[nt][2] = f2t(p10);
            pe[nt][3] = f2t(p11);
        }
        sum0 += __shfl_xor_sync(0xffffffffu, sum0, 1);
        sum0 += __shfl_xor_sync(0xffffffffu, sum0, 2);
        sum1 += __shfl_xor_sync(0xffffffffu, sum1, 1);
        sum1 += __shfl_xor_sync(0xffffffffu, sum1, 2);
        lrow0 = lrow0 * sc0 + sum0;
        lrow1 = lrow1 * sc1 + sum1;
        mrow0 = mn0; mrow1 = mn1;
        #pragma unroll
        for (int nt = 0; nt < 8; nt++){
            o[nt][0] *= sc0; o[nt][1] *= sc0;
            o[nt][2] *= sc1; o[nt][3] *= sc1;
        }

        // O += P V  (P A-fragments via in-warp shuffle transpose; V via ldmatrix)
        #pragma unroll
        for (int k2 = 0; k2 < 8; k2++){
            unsigned pa[4];
            unsigned v0 = __shfl_sync(0xffffffffu, pe[k2][0], srcA);
            unsigned v1 = __shfl_sync(0xffffffffu, pe[k2][1], srcA);
            pa[0] = todd ? v1 : v0;
            unsigned w0 = __shfl_sync(0xffffffffu, pe[k2][2], srcA);
            unsigned w1 = __shfl_sync(0xffffffffu, pe[k2][3], srcA);
            pa[1] = todd ? w1 : w0;
            unsigned x0 = __shfl_sync(0xffffffffu, pe[k2][0], srcB);
            unsigned x1 = __shfl_sync(0xffffffffu, pe[k2][1], srcB);
            pa[2] = todd ? x1 : x0;
            unsigned y0 = __shfl_sync(0xffffffffu, pe[k2][2], srcB);
            unsigned y1 = __shfl_sync(0xffffffffu, pe[k2][3], srcB);
            pa[3] = todd ? y1 : y0;
            #pragma unroll
            for (int np = 0; np < 4; np++){
                unsigned u0, u1, u2, u3;
                ldsm4(u0, u1, u2, u3, vbase + 4u*KSW(np*16 + lrow, k2*8 + lcol));
                mma8(o[2*np  ], pa, u0, u2);
                mma8(o[2*np+1], pa, u1, u3);
            }
        }
    }

    // epilogue: O /= l, rna-rounded
    float i0 = 1.f / lrow0, i1 = 1.f / lrow1;
    int b = bh >> 4, h = bh & 15;
    float* Op  = g_o + (size_t)(b*TSEQ + qrow0 + g)*DMODEL + h*64;
    float* Op8 = Op + (size_t)8*DMODEL;
    #pragma unroll
    for (int nt = 0; nt < 8; nt++){
        int d = nt*8 + 2*tg;
        Op [d]   = rnaf(o[nt][0] * i0);
        Op [d+1] = rnaf(o[nt][1] * i0);
        Op8[d]   = rnaf(o[nt][2] * i1);
        Op8[d+1] = rnaf(o[nt][3] * i1);
    }
}

extern "C" void kernel_launch(void* const* d_in, const int* in_sizes, int n_in,
                              void* d_out, int out_size)
{
    const float* x     = (const float*)d_in[0];
    const float* wqkv  = (const float*)d_in[1];
    const float* wproj = (const float*)d_in[2];
    const float* bproj = (const float*)d_in[3];
    float* out = (float*)d_out;

    cudaFuncSetAttribute(gemm2<0>, cudaFuncAttributeMaxDynamicSharedMemorySize, GEMM_SMEM);
    cudaFuncSetAttribute(gemm2<1>, cudaFuncAttributeMaxDynamicSharedMemorySize, GEMM_SMEM);
    cudaFuncSetAttribute(attn_kernel, cudaFuncAttributeMaxDynamicSharedMemorySize, ATTN_SMEM);

    float* pbq; cudaGetSymbolAddress((void**)&pbq, g_bqkv);
    float* pbp; cudaGetSymbolAddress((void**)&pbp, g_bproj);

    transpose_round<<<dim3(3072/32, 1024/32), dim3(32, 8)>>>(wqkv, pbq, 1024, 3072);
    transpose_round<<<dim3(1024/32, 1024/32), dim3(32, 8)>>>(wproj, pbp, 1024, 1024);

    gemm2<0><<<dim3(24, 64), 128, GEMM_SMEM>>>(x, pbq, nullptr, nullptr);
    attn_kernel<<<dim3(32, 64), 128, ATTN_SMEM>>>();
    gemm2<1><<<dim3(8, 64), 128, GEMM_SMEM>>>(nullptr, pbp, bproj, out);
}